// round 2
// baseline (speedup 1.0000x reference)
#include <cuda_runtime.h>
#include <cuda_bf16.h>

#define BLOCK 256
#define GPB   (BLOCK * 2)   // gaussians per block

__device__ __forceinline__ void compute_one(
    float4 q, float s0r, float s1r, float s2r, float orw,
    float* sc, float* scol, const float4* feat4, long long fi,
    float4* cov2d4, float* opacity, int i)
{
    float inv = rsqrtf(q.x * q.x + q.y * q.y + q.z * q.z + q.w * q.w);
    float w = q.x * inv, x = q.y * inv, y = q.z * inv, z = q.w * inv;

    float R00 = 1.f - 2.f * (y * y + z * z);
    float R01 = 2.f * (x * y - w * z);
    float R02 = 2.f * (x * z + w * y);
    float R10 = 2.f * (x * y + w * z);
    float R11 = 1.f - 2.f * (x * x + z * z);
    float R12 = 2.f * (y * z - w * x);
    float R20 = 2.f * (x * z - w * y);
    float R21 = 2.f * (y * z + w * x);
    float R22 = 1.f - 2.f * (x * x + y * y);

    float s0 = __expf(2.f * s0r);
    float s1 = __expf(2.f * s1r);
    float s2 = __expf(2.f * s2r);

    float c00 = R00 * R00 * s0 + R01 * R01 * s1 + R02 * R02 * s2;
    float c01 = R00 * R10 * s0 + R01 * R11 * s1 + R02 * R12 * s2;
    float c02 = R00 * R20 * s0 + R01 * R21 * s1 + R02 * R22 * s2;
    float c11 = R10 * R10 * s0 + R11 * R11 * s1 + R12 * R12 * s2;
    float c12 = R10 * R20 * s0 + R11 * R21 * s1 + R12 * R22 * s2;
    float c22 = R20 * R20 * s0 + R21 * R21 * s1 + R22 * R22 * s2;

    sc[0] = c00; sc[1] = c01; sc[2] = c02;
    sc[3] = c01; sc[4] = c11; sc[5] = c12;
    sc[6] = c02; sc[7] = c12; sc[8] = c22;

    float var = (c00 + c11 + c22) * (1.0f / 3.0f);
    cov2d4[i] = make_float4(var, 0.f, 0.f, var);

    float4 f = feat4[fi];   // first 4 floats of the 48-float row (need 3)
    scol[0] = f.x; scol[1] = f.y; scol[2] = f.z;

    opacity[i] = 1.0f / (1.0f + __expf(-orw));
}

__global__ __launch_bounds__(BLOCK)
void gaussian_pre_kernel(
    const float*  __restrict__ scaling_raw,  // [N,3]
    const float4* __restrict__ rotation,     // [N,4]
    const float*  __restrict__ opacity_raw,  // [N]
    const float4* __restrict__ features4,    // [N,16,3] viewed as float4, row stride 12
    float* __restrict__ cov3d,               // [N,9]
    float4* __restrict__ cov2d4,             // [N,4] as float4
    float* __restrict__ color,               // [N,3]
    float* __restrict__ opacity,             // [N]
    int N)
{
    __shared__ float s_cov[GPB * 9];
    __shared__ float s_col[GPB * 3];

    const int tid  = threadIdx.x;
    const int base = blockIdx.x * GPB;
    const int i0   = base + tid;
    const int i1   = i0 + BLOCK;
    const int cnt  = min(GPB, N - base);

    // ---- issue all global loads up front (max MLP) ----
    float4 q0, q1;
    float sa0 = 0.f, sb0 = 0.f, sc0 = 0.f, op0 = 0.f;
    float sa1 = 0.f, sb1 = 0.f, sc1 = 0.f, op1 = 0.f;
    bool v0 = i0 < N, v1 = i1 < N;

    if (v0) {
        q0  = rotation[i0];
        sa0 = scaling_raw[3 * i0 + 0];
        sb0 = scaling_raw[3 * i0 + 1];
        sc0 = scaling_raw[3 * i0 + 2];
        op0 = opacity_raw[i0];
    }
    if (v1) {
        q1  = rotation[i1];
        sa1 = scaling_raw[3 * i1 + 0];
        sb1 = scaling_raw[3 * i1 + 1];
        sc1 = scaling_raw[3 * i1 + 2];
        op1 = opacity_raw[i1];
    }

    if (v0) compute_one(q0, sa0, sb0, sc0, op0,
                        &s_cov[tid * 9], &s_col[tid * 3],
                        features4, (long long)i0 * 12, cov2d4, opacity, i0);
    if (v1) compute_one(q1, sa1, sb1, sc1, op1,
                        &s_cov[(tid + BLOCK) * 9], &s_col[(tid + BLOCK) * 3],
                        features4, (long long)i1 * 12, cov2d4, opacity, i1);

    __syncthreads();

    // ---- coalesced vectorized flush ----
    {
        const int n9 = cnt * 9;
        float* dst = cov3d + (long long)base * 9;   // 16B aligned (base*36 bytes, base mult of 512)
        const int nv = n9 >> 2;
        const float4* s4 = reinterpret_cast<const float4*>(s_cov);
        float4* d4 = reinterpret_cast<float4*>(dst);
        for (int j = tid; j < nv; j += BLOCK) d4[j] = s4[j];
        for (int j = (nv << 2) + tid; j < n9; j += BLOCK) dst[j] = s_cov[j];
    }
    {
        const int n3 = cnt * 3;
        float* dst = color + (long long)base * 3;
        const int nv = n3 >> 2;
        const float4* s4 = reinterpret_cast<const float4*>(s_col);
        float4* d4 = reinterpret_cast<float4*>(dst);
        for (int j = tid; j < nv; j += BLOCK) d4[j] = s4[j];
        for (int j = (nv << 2) + tid; j < n3; j += BLOCK) dst[j] = s_col[j];
    }
}

extern "C" void kernel_launch(void* const* d_in, const int* in_sizes, int n_in,
                              void* d_out, int out_size) {
    // inputs: 0 xyz[N,3], 1 scaling_raw[N,3], 2 rotation[N,4], 3 opacity_raw[N,1],
    //         4 features[N,16,3], 5 viewmatrix[4,4], 6 projmatrix[4,4]
    const float*  scaling  = (const float*) d_in[1];
    const float4* rotation = (const float4*)d_in[2];
    const float*  opac_raw = (const float*) d_in[3];
    const float4* features = (const float4*)d_in[4];

    const int N = in_sizes[3];

    float* out    = (float*)d_out;
    float*  cov3d = out;                                          // 9N
    float4* cov2d = (float4*)(out + (long long)9 * N);            // 4N
    float*  color = out + (long long)13 * N;                      // 3N
    float*  opac  = out + (long long)16 * N;                      // N

    int grid = (N + GPB - 1) / GPB;
    gaussian_pre_kernel<<<grid, BLOCK>>>(scaling, rotation, opac_raw, features,
                                         cov3d, cov2d, color, opac, N);
}

// round 3
// speedup vs baseline: 1.0087x; 1.0087x over previous
#include <cuda_runtime.h>
#include <cuda_bf16.h>

#define BLOCK 256
#define NWARP (BLOCK / 32)

__global__ __launch_bounds__(BLOCK)
void gaussian_pre_kernel(
    const float*  __restrict__ scaling_raw,  // [N,3]
    const float4* __restrict__ rotation,     // [N,4]
    const float*  __restrict__ opacity_raw,  // [N]
    const float4* __restrict__ features4,    // [N,16,3] as float4, row stride 12
    float* __restrict__ cov3d,               // [N,9]
    float4* __restrict__ cov2d4,             // [N,4] as float4
    float* __restrict__ color,               // [N,3]
    float* __restrict__ opacity,             // [N]
    int N)
{
    __shared__ float s_cov[BLOCK * 9];
    __shared__ float s_col[BLOCK * 3];

    const int tid  = threadIdx.x;
    const int lane = tid & 31;
    const int wrp  = tid >> 5;
    const int wbase = blockIdx.x * BLOCK + wrp * 32;  // first gaussian of this warp
    const int i     = wbase + lane;

    float* s_cov_w = s_cov + wrp * 32 * 9;   // 288 floats, 1152B-aligned
    float* s_col_w = s_col + wrp * 32 * 3;   // 96 floats,  384B-aligned

    if (i < N) {
        // quaternion -> rotation matrix (normalized)
        float4 q = rotation[i];
        float inv = rsqrtf(q.x * q.x + q.y * q.y + q.z * q.z + q.w * q.w);
        float w = q.x * inv, x = q.y * inv, y = q.z * inv, z = q.w * inv;

        float R00 = 1.f - 2.f * (y * y + z * z);
        float R01 = 2.f * (x * y - w * z);
        float R02 = 2.f * (x * z + w * y);
        float R10 = 2.f * (x * y + w * z);
        float R11 = 1.f - 2.f * (x * x + z * z);
        float R12 = 2.f * (y * z - w * x);
        float R20 = 2.f * (x * z - w * y);
        float R21 = 2.f * (y * z + w * x);
        float R22 = 1.f - 2.f * (x * x + y * y);

        // sigma^2 = exp(2*scaling)
        float s0 = __expf(2.f * scaling_raw[3 * i + 0]);
        float s1 = __expf(2.f * scaling_raw[3 * i + 1]);
        float s2 = __expf(2.f * scaling_raw[3 * i + 2]);

        float c00 = R00 * R00 * s0 + R01 * R01 * s1 + R02 * R02 * s2;
        float c01 = R00 * R10 * s0 + R01 * R11 * s1 + R02 * R12 * s2;
        float c02 = R00 * R20 * s0 + R01 * R21 * s1 + R02 * R22 * s2;
        float c11 = R10 * R10 * s0 + R11 * R11 * s1 + R12 * R12 * s2;
        float c12 = R10 * R20 * s0 + R11 * R21 * s1 + R12 * R22 * s2;
        float c22 = R20 * R20 * s0 + R21 * R21 * s1 + R22 * R22 * s2;

        float* sc = &s_cov_w[lane * 9];      // stride 9: bank-conflict-free
        sc[0] = c00; sc[1] = c01; sc[2] = c02;
        sc[3] = c01; sc[4] = c11; sc[5] = c12;
        sc[6] = c02; sc[7] = c12; sc[8] = c22;

        float var = (c00 + c11 + c22) * (1.0f / 3.0f);
        cov2d4[i] = make_float4(var, 0.f, 0.f, var);

        float4 f = features4[(long long)i * 12];  // first 16B of 192B row
        s_col_w[lane * 3 + 0] = f.x;
        s_col_w[lane * 3 + 1] = f.y;
        s_col_w[lane * 3 + 2] = f.z;

        float o = opacity_raw[i];
        opacity[i] = 1.0f / (1.0f + __expf(-o));
    }
    __syncwarp();

    const int cnt = min(32, N - wbase);   // gaussians this warp actually owns
    if (cnt == 32) {
        // fast path: full warp — vectorized flush
        const float4* s4 = reinterpret_cast<const float4*>(s_cov_w);
        float4* d4 = reinterpret_cast<float4*>(cov3d + (long long)wbase * 9);
        #pragma unroll
        for (int j = 0; j < 2; j++) d4[lane + 32 * j] = s4[lane + 32 * j];
        if (lane < 8) d4[lane + 64] = s4[lane + 64];            // 72 total

        const float4* c4 = reinterpret_cast<const float4*>(s_col_w);
        float4* e4 = reinterpret_cast<float4*>(color + (long long)wbase * 3);
        if (lane < 24) e4[lane] = c4[lane];                     // 24 total
    } else if (cnt > 0) {
        // tail: scalar flush
        const int n9 = cnt * 9;
        float* dst9 = cov3d + (long long)wbase * 9;
        for (int j = lane; j < n9; j += 32) dst9[j] = s_cov_w[j];
        const int n3 = cnt * 3;
        float* dst3 = color + (long long)wbase * 3;
        for (int j = lane; j < n3; j += 32) dst3[j] = s_col_w[j];
    }
}

extern "C" void kernel_launch(void* const* d_in, const int* in_sizes, int n_in,
                              void* d_out, int out_size) {
    // inputs: 0 xyz[N,3], 1 scaling_raw[N,3], 2 rotation[N,4], 3 opacity_raw[N,1],
    //         4 features[N,16,3], 5 viewmatrix[4,4], 6 projmatrix[4,4]
    const float*  scaling  = (const float*) d_in[1];
    const float4* rotation = (const float4*)d_in[2];
    const float*  opac_raw = (const float*) d_in[3];
    const float4* features = (const float4*)d_in[4];

    const int N = in_sizes[3];

    float* out    = (float*)d_out;
    float*  cov3d = out;                                  // 9N
    float4* cov2d = (float4*)(out + (long long)9 * N);    // 4N
    float*  color = out + (long long)13 * N;              // 3N
    float*  opac  = out + (long long)16 * N;              // N

    int grid = (N + BLOCK - 1) / BLOCK;
    gaussian_pre_kernel<<<grid, BLOCK>>>(scaling, rotation, opac_raw, features,
                                         cov3d, cov2d, color, opac, N);
}